// round 8
// baseline (speedup 1.0000x reference)
#include <cuda_runtime.h>
#include <cstdint>

// Segment mean readout (R5 config + occupancy push):
//   in0: atom_hiddens  float32 [1e6, 300]
//   in1: a_scope       int32   [50000, 2] (start, size), contiguous segments
//   out: mol_vecs      float32 [50000, 300]
//
// One warp per graph. Row = 75 float4 (1200 B). Lane l covers float4 cols
// l, l+32, l+64 (predicated l<11).
// Loads .lu, stores .cs (best policy pair from R3-R5 sweep).
// NEW: __launch_bounds__(256, 6) caps regs at 40 -> 6 blocks/SM (48 warps,
// 75% theoretical vs 62.5%). Session data shows DRAM% tracks warp count
// (occ 47%->83% DRAM, 56%->87%); buying warps is cheaper than buying
// per-warp MLP (R6 disproved the latter).

#define VEC_PER_ROW 75

__global__ void __launch_bounds__(256, 6)
readout_mean_kernel(const float4* __restrict__ x,
                    const int* __restrict__ scope,
                    float4* __restrict__ out,
                    int n_graphs) {
    const int gwarp = (blockIdx.x * blockDim.x + threadIdx.x) >> 5;
    const int lane  = threadIdx.x & 31;
    if (gwarp >= n_graphs) return;

    const int start = scope[2 * gwarp];
    const int size  = scope[2 * gwarp + 1];

    float4 a0 = make_float4(0.f, 0.f, 0.f, 0.f);
    float4 a1 = make_float4(0.f, 0.f, 0.f, 0.f);
    float4 a2 = make_float4(0.f, 0.f, 0.f, 0.f);

    const bool has3 = (lane < VEC_PER_ROW - 64);  // lane < 11

    const float4* p = x + (long long)start * VEC_PER_ROW + lane;

    int r = 0;
    // 2x software pipeline: 6 independent last-use loads in flight.
    for (; r + 2 <= size; r += 2, p += 2 * VEC_PER_ROW) {
        float4 v00 = __ldlu(p);
        float4 v01 = __ldlu(p + 32);
        float4 v10 = __ldlu(p + VEC_PER_ROW);
        float4 v11 = __ldlu(p + VEC_PER_ROW + 32);
        float4 v02, v12;
        if (has3) {
            v02 = __ldlu(p + 64);
            v12 = __ldlu(p + VEC_PER_ROW + 64);
        }
        a0.x += v00.x; a0.y += v00.y; a0.z += v00.z; a0.w += v00.w;
        a1.x += v01.x; a1.y += v01.y; a1.z += v01.z; a1.w += v01.w;
        a0.x += v10.x; a0.y += v10.y; a0.z += v10.z; a0.w += v10.w;
        a1.x += v11.x; a1.y += v11.y; a1.z += v11.z; a1.w += v11.w;
        if (has3) {
            a2.x += v02.x; a2.y += v02.y; a2.z += v02.z; a2.w += v02.w;
            a2.x += v12.x; a2.y += v12.y; a2.z += v12.z; a2.w += v12.w;
        }
    }
    for (; r < size; ++r, p += VEC_PER_ROW) {
        float4 v0 = __ldlu(p);
        float4 v1 = __ldlu(p + 32);
        a0.x += v0.x; a0.y += v0.y; a0.z += v0.z; a0.w += v0.w;
        a1.x += v1.x; a1.y += v1.y; a1.z += v1.z; a1.w += v1.w;
        if (has3) {
            float4 v2 = __ldlu(p + 64);
            a2.x += v2.x; a2.y += v2.y; a2.z += v2.z; a2.w += v2.w;
        }
    }

    // denom = max(size,1); size==0 -> zeros (matches reference's where()).
    const float inv = (size > 0) ? (1.0f / (float)size) : 0.0f;

    float4* o = out + (long long)gwarp * VEC_PER_ROW + lane;
    __stcs(o,      make_float4(a0.x * inv, a0.y * inv, a0.z * inv, a0.w * inv));
    __stcs(o + 32, make_float4(a1.x * inv, a1.y * inv, a1.z * inv, a1.w * inv));
    if (has3) {
        __stcs(o + 64, make_float4(a2.x * inv, a2.y * inv, a2.z * inv, a2.w * inv));
    }
}

extern "C" void kernel_launch(void* const* d_in, const int* in_sizes, int n_in,
                              void* d_out, int out_size) {
    const float4* x = (const float4*)d_in[0];   // atom_hiddens f32 [1e6,300]
    const int* scope = (const int*)d_in[1];     // a_scope int32 [50000,2]
    float4* out = (float4*)d_out;

    const int n_graphs = in_sizes[1] / 2;       // 100000 ints -> 50000 graphs
    const int threads = 256;                    // 8 warps/block
    const int blocks = (n_graphs * 32 + threads - 1) / threads;

    readout_mean_kernel<<<blocks, threads>>>(x, scope, out, n_graphs);
}

// round 9
// speedup vs baseline: 1.0166x; 1.0166x over previous
#include <cuda_runtime.h>
#include <cstdint>

// Segment mean readout — FINAL (R5 config; session best 181.0us, 87.1% DRAM, 6908 GB/s).
//   in0: atom_hiddens  float32 [1e6, 300]
//   in1: a_scope       int32   [50000, 2] (start, size), contiguous segments
//   out: mol_vecs      float32 [50000, 300]
//
// One warp per graph. Row = 75 float4 (1200 B). Lane l covers float4 cols
// l, l+32, l+64 (predicated l<11).
// Loads:  .lu (last-use — discard L2 line after the single read)
// Stores: .cs (evict-first write-back — keeps 128B dirty-line coalescing)
//
// Swept and rejected (bracketing the optimum):
//  - pipeline depth: 1-row (190.5us) / 2-row (181.0us, THIS) / 4-row (191.1us, occ 47%)
//  - cache policy: plain(190.5) / .cs/.cs(182.8) / .lu/.wt(184.8) / .lu/.cs(181.0, THIS)
//  - occupancy: regs 40 via launch_bounds (186.1us — narrower load window beat
//    the extra warps; DRAM 84.4%) / regs 48 (THIS, 87.1%) / regs 51 (82.8%)
// DRAM traffic == irreducible 1.26 GB (overfetch ~0) -> at the mixed-stream roofline.

#define VEC_PER_ROW 75

__global__ void __launch_bounds__(256)
readout_mean_kernel(const float4* __restrict__ x,
                    const int* __restrict__ scope,
                    float4* __restrict__ out,
                    int n_graphs) {
    const int gwarp = (blockIdx.x * blockDim.x + threadIdx.x) >> 5;
    const int lane  = threadIdx.x & 31;
    if (gwarp >= n_graphs) return;

    const int start = scope[2 * gwarp];
    const int size  = scope[2 * gwarp + 1];

    float4 a0 = make_float4(0.f, 0.f, 0.f, 0.f);
    float4 a1 = make_float4(0.f, 0.f, 0.f, 0.f);
    float4 a2 = make_float4(0.f, 0.f, 0.f, 0.f);

    const bool has3 = (lane < VEC_PER_ROW - 64);  // lane < 11

    const float4* p = x + (long long)start * VEC_PER_ROW + lane;

    int r = 0;
    // 2x software pipeline: 6 independent last-use loads in flight.
    for (; r + 2 <= size; r += 2, p += 2 * VEC_PER_ROW) {
        float4 v00 = __ldlu(p);
        float4 v01 = __ldlu(p + 32);
        float4 v10 = __ldlu(p + VEC_PER_ROW);
        float4 v11 = __ldlu(p + VEC_PER_ROW + 32);
        float4 v02, v12;
        if (has3) {
            v02 = __ldlu(p + 64);
            v12 = __ldlu(p + VEC_PER_ROW + 64);
        }
        a0.x += v00.x; a0.y += v00.y; a0.z += v00.z; a0.w += v00.w;
        a1.x += v01.x; a1.y += v01.y; a1.z += v01.z; a1.w += v01.w;
        a0.x += v10.x; a0.y += v10.y; a0.z += v10.z; a0.w += v10.w;
        a1.x += v11.x; a1.y += v11.y; a1.z += v11.z; a1.w += v11.w;
        if (has3) {
            a2.x += v02.x; a2.y += v02.y; a2.z += v02.z; a2.w += v02.w;
            a2.x += v12.x; a2.y += v12.y; a2.z += v12.z; a2.w += v12.w;
        }
    }
    for (; r < size; ++r, p += VEC_PER_ROW) {
        float4 v0 = __ldlu(p);
        float4 v1 = __ldlu(p + 32);
        a0.x += v0.x; a0.y += v0.y; a0.z += v0.z; a0.w += v0.w;
        a1.x += v1.x; a1.y += v1.y; a1.z += v1.z; a1.w += v1.w;
        if (has3) {
            float4 v2 = __ldlu(p + 64);
            a2.x += v2.x; a2.y += v2.y; a2.z += v2.z; a2.w += v2.w;
        }
    }

    // denom = max(size,1); size==0 -> zeros (matches reference's where()).
    const float inv = (size > 0) ? (1.0f / (float)size) : 0.0f;

    float4* o = out + (long long)gwarp * VEC_PER_ROW + lane;
    __stcs(o,      make_float4(a0.x * inv, a0.y * inv, a0.z * inv, a0.w * inv));
    __stcs(o + 32, make_float4(a1.x * inv, a1.y * inv, a1.z * inv, a1.w * inv));
    if (has3) {
        __stcs(o + 64, make_float4(a2.x * inv, a2.y * inv, a2.z * inv, a2.w * inv));
    }
}

extern "C" void kernel_launch(void* const* d_in, const int* in_sizes, int n_in,
                              void* d_out, int out_size) {
    const float4* x = (const float4*)d_in[0];   // atom_hiddens f32 [1e6,300]
    const int* scope = (const int*)d_in[1];     // a_scope int32 [50000,2]
    float4* out = (float4*)d_out;

    const int n_graphs = in_sizes[1] / 2;       // 100000 ints -> 50000 graphs
    const int threads = 256;                    // 8 warps/block
    const int blocks = (n_graphs * 32 + threads - 1) / threads;

    readout_mean_kernel<<<blocks, threads>>>(x, scope, out, n_graphs);
}

// round 10
// speedup vs baseline: 1.0299x; 1.0131x over previous
#include <cuda_runtime.h>
#include <cstdint>

// Segment mean readout — FINAL (converged; 3x reproduced at 181-183us, 87% DRAM, ~6.9 TB/s).
//   in0: atom_hiddens  float32 [1e6, 300]
//   in1: a_scope       int32   [50000, 2] (start, size), contiguous segments
//   out: mol_vecs      float32 [50000, 300]
//
// One warp per graph. Row = 75 float4 (1200 B). Lane l covers float4 cols
// l, l+32, l+64 (predicated l<11).
// Loads:  .lu (last-use — discard L2 line after the single read)
// Stores: .cs (evict-first write-back — keeps 128B dirty-line coalescing)
//
// Bracketed sweeps (all rejected alternatives measured):
//  - pipeline depth: 1-row 190.5us / 2-row 181.0us (THIS) / 4-row 191.1us
//  - cache policy:  plain 190.5 / .cs/.cs 182.8 / .lu/.wt 184.8 / .lu/.cs 181.0 (THIS)
//  - occupancy:     regs 40 -> 186.1us / regs 48 (THIS) / regs 51 -> 191.1us
// Achieved DRAM traffic == irreducible 1.26 GB (overfetch ~0); 87% sustained DRAM
// on a 95R/5W mixed stream is the chip's practical ceiling (LTS-cap limited).

#define VEC_PER_ROW 75

__global__ void __launch_bounds__(256)
readout_mean_kernel(const float4* __restrict__ x,
                    const int* __restrict__ scope,
                    float4* __restrict__ out,
                    int n_graphs) {
    const int gwarp = (blockIdx.x * blockDim.x + threadIdx.x) >> 5;
    const int lane  = threadIdx.x & 31;
    if (gwarp >= n_graphs) return;

    const int start = scope[2 * gwarp];
    const int size  = scope[2 * gwarp + 1];

    float4 a0 = make_float4(0.f, 0.f, 0.f, 0.f);
    float4 a1 = make_float4(0.f, 0.f, 0.f, 0.f);
    float4 a2 = make_float4(0.f, 0.f, 0.f, 0.f);

    const bool has3 = (lane < VEC_PER_ROW - 64);  // lane < 11

    const float4* p = x + (long long)start * VEC_PER_ROW + lane;

    int r = 0;
    // 2x software pipeline: 6 independent last-use loads in flight.
    for (; r + 2 <= size; r += 2, p += 2 * VEC_PER_ROW) {
        float4 v00 = __ldlu(p);
        float4 v01 = __ldlu(p + 32);
        float4 v10 = __ldlu(p + VEC_PER_ROW);
        float4 v11 = __ldlu(p + VEC_PER_ROW + 32);
        float4 v02, v12;
        if (has3) {
            v02 = __ldlu(p + 64);
            v12 = __ldlu(p + VEC_PER_ROW + 64);
        }
        a0.x += v00.x; a0.y += v00.y; a0.z += v00.z; a0.w += v00.w;
        a1.x += v01.x; a1.y += v01.y; a1.z += v01.z; a1.w += v01.w;
        a0.x += v10.x; a0.y += v10.y; a0.z += v10.z; a0.w += v10.w;
        a1.x += v11.x; a1.y += v11.y; a1.z += v11.z; a1.w += v11.w;
        if (has3) {
            a2.x += v02.x; a2.y += v02.y; a2.z += v02.z; a2.w += v02.w;
            a2.x += v12.x; a2.y += v12.y; a2.z += v12.z; a2.w += v12.w;
        }
    }
    for (; r < size; ++r, p += VEC_PER_ROW) {
        float4 v0 = __ldlu(p);
        float4 v1 = __ldlu(p + 32);
        a0.x += v0.x; a0.y += v0.y; a0.z += v0.z; a0.w += v0.w;
        a1.x += v1.x; a1.y += v1.y; a1.z += v1.z; a1.w += v1.w;
        if (has3) {
            float4 v2 = __ldlu(p + 64);
            a2.x += v2.x; a2.y += v2.y; a2.z += v2.z; a2.w += v2.w;
        }
    }

    // denom = max(size,1); size==0 -> zeros (matches reference's where()).
    const float inv = (size > 0) ? (1.0f / (float)size) : 0.0f;

    float4* o = out + (long long)gwarp * VEC_PER_ROW + lane;
    __stcs(o,      make_float4(a0.x * inv, a0.y * inv, a0.z * inv, a0.w * inv));
    __stcs(o + 32, make_float4(a1.x * inv, a1.y * inv, a1.z * inv, a1.w * inv));
    if (has3) {
        __stcs(o + 64, make_float4(a2.x * inv, a2.y * inv, a2.z * inv, a2.w * inv));
    }
}

extern "C" void kernel_launch(void* const* d_in, const int* in_sizes, int n_in,
                              void* d_out, int out_size) {
    const float4* x = (const float4*)d_in[0];   // atom_hiddens f32 [1e6,300]
    const int* scope = (const int*)d_in[1];     // a_scope int32 [50000,2]
    float4* out = (float4*)d_out;

    const int n_graphs = in_sizes[1] / 2;       // 100000 ints -> 50000 graphs
    const int threads = 256;                    // 8 warps/block
    const int blocks = (n_graphs * 32 + threads - 1) / threads;

    readout_mean_kernel<<<blocks, threads>>>(x, scope, out, n_graphs);
}